// round 13
// baseline (speedup 1.0000x reference)
#include <cuda_runtime.h>
#include <cuda_fp16.h>
#include <math.h>

#define BQ 16
#define NQ 4096
#define SQ 1024
#define KQ 32
#define CQ 64
#define HQ 128
#define CAND_CAP 768
#define PWORDS 4608   // 9kt * 4mi * 32 lanes * 4 words (one A buffer)

__device__ int g_group_idx[BQ * SQ * KQ];

// fp16 B-fragments packed as uint4 (two adjacent nt fragments per thread):
// index = (kt*8 + wn*2 + ntp)*32 + lane;  lane = g*4+tg.
__device__ uint4 g_W1h[5 * 256];
__device__ uint4 g_W2h[8 * 256];
__device__ uint4 g_W3h[9 * 256];
__device__ uint4 g_W4h[8 * 256];

__device__ __forceinline__ unsigned f2h2(float lo, float hi) {
    __half2 h = __floats2half2_rn(lo, hi);
    return *(unsigned*)&h;
}
__device__ __forceinline__ float2 h22f2(unsigned u) {
    __half2 h = *(__half2*)&u;
    return __half22float2(h);
}
__device__ __forceinline__ void mma_f16(
    float& d0, float& d1, float& d2, float& d3,
    unsigned a0, unsigned a1, unsigned a2, unsigned a3,
    unsigned b0, unsigned b1)
{
    asm("mma.sync.aligned.m16n8k16.row.col.f32.f16.f16.f32 "
        "{%0,%1,%2,%3}, {%4,%5,%6,%7}, {%8,%9}, {%0,%1,%2,%3};"
        : "+f"(d0), "+f"(d1), "+f"(d2), "+f"(d3)
        : "r"(a0), "r"(a1), "r"(a2), "r"(a3), "r"(b0), "r"(b1));
}

// packed f32x2 helpers (FPS)
__device__ __forceinline__ unsigned long long add2(
    unsigned long long a, unsigned long long b)
{
    unsigned long long d;
    asm("add.rn.f32x2 %0, %1, %2;" : "=l"(d) : "l"(a), "l"(b));
    return d;
}
__device__ __forceinline__ unsigned long long mul2(
    unsigned long long a, unsigned long long b)
{
    unsigned long long d;
    asm("mul.rn.f32x2 %0, %1, %2;" : "=l"(d) : "l"(a), "l"(b));
    return d;
}
__device__ __forceinline__ unsigned long long fma2(
    unsigned long long a, unsigned long long b, unsigned long long c)
{
    unsigned long long d;
    asm("fma.rn.f32x2 %0, %1, %2, %3;" : "=l"(d) : "l"(a), "l"(b), "l"(c));
    return d;
}
__device__ __forceinline__ unsigned long long bcast2(float w)
{
    unsigned long long d; unsigned u = __float_as_uint(w);
    asm("mov.b64 %0, {%1, %1};" : "=l"(d) : "r"(u));
    return d;
}
__device__ __forceinline__ float2 unpk2(unsigned long long a)
{
    float2 f;
    asm("mov.b64 {%0, %1}, %2;" : "=f"(f.x), "=f"(f.y) : "l"(a));
    return f;
}

// fragment-major A index for m16n8k16 (word = fp16x2 pair):
__device__ __forceinline__ int pidx16(int r, int pi) {
    int kt = pi >> 3, pp = pi & 7;
    int ls = (r & 7) * 4 + (pp & 3);
    int reg = ((r >> 3) & 1) + 2 * ((pp >> 2) & 1);
    return (((kt * 4 + (r >> 4)) * 32 + ls) << 2) + reg;
}

// ---------------------------------------------------------------------------
// Kernel 0: pack weights into per-thread fp16 uint4 B-fragments w/ col perm.
// ---------------------------------------------------------------------------
__device__ __forceinline__ float getw(const float* __restrict__ W,
                                      int k, int n, int mode)
{
    int r;
    if (mode == 0)      r = (k < 128) ? k       : -1;
    else if (mode == 1) r = (k < 64)  ? k + 3   : (k < 67  ? k - 64  : -1);
    else                r = (k < 128) ? k + 3   : (k < 131 ? k - 128 : -1);
    return (r >= 0) ? W[r * 128 + n] : 0.f;
}
__device__ __forceinline__ void pack16(int i, int KT, int mode,
                                       const float* __restrict__ W, uint4* out)
{
    if (i < KT * 256) {
        int kt = i >> 8, rem = i & 255;
        int w = rem >> 5, lane = rem & 31;
        int wn = w >> 1, ntp = w & 1;
        int g = lane >> 2, tg = lane & 3;
        int nc0 = wn * 32 + (2 * ntp) * 8 + g;
        int nc1 = nc0 + 8;
        int k0 = 16 * kt + 2 * tg;
        out[i] = make_uint4(
            f2h2(getw(W, k0,     nc0, mode), getw(W, k0 + 1, nc0, mode)),
            f2h2(getw(W, k0 + 8, nc0, mode), getw(W, k0 + 9, nc0, mode)),
            f2h2(getw(W, k0,     nc1, mode), getw(W, k0 + 1, nc1, mode)),
            f2h2(getw(W, k0 + 8, nc1, mode), getw(W, k0 + 9, nc1, mode)));
    }
}
__global__ void cvt_w_kernel(const float* __restrict__ W1,
                             const float* __restrict__ W2,
                             const float* __restrict__ W3,
                             const float* __restrict__ W4)
{
    int i = blockIdx.x * 256 + threadIdx.x;
    pack16(i, 5, 1, W1, g_W1h);
    pack16(i, 8, 0, W2, g_W2h);
    pack16(i, 9, 2, W3, g_W3h);
    pack16(i, 8, 0, W4, g_W4h);
}

// ---------------------------------------------------------------------------
// Kernel 1: FPS (unchanged — math must stay bit-identical).
// ---------------------------------------------------------------------------
__global__ __launch_bounds__(512) void fps_kernel(
    const float* __restrict__ xyz, float* __restrict__ new_xyz)
{
    const int b = blockIdx.x;
    const int t = threadIdx.x;
    const int lane = t & 31;
    const int warp = t >> 5;
    extern __shared__ float sm[];
    float* xs = sm;
    float* ys = sm + NQ;
    float* zs = sm + 2 * NQ;
    __shared__ unsigned sv[2][16];
    __shared__ int      si[2][16];

    const float* xb = xyz + (size_t)b * NQ * 3;
    for (int idx = t; idx < NQ * 3; idx += 512) {
        float v = xb[idx];
        int p = idx / 3;
        int j = idx - 3 * p;
        if (j == 0) xs[p] = v; else if (j == 1) ys[p] = v; else zs[p] = v;
    }
    __syncthreads();

    unsigned long long px2[4], py2[4], pz2[4];
    float dmin[8];
#pragma unroll
    for (int q = 0; q < 4; q++) {
        int p0 = t + ((2 * q) << 9), p1 = t + ((2 * q + 1) << 9);
        px2[q] = (unsigned long long)__float_as_uint(xs[p0]) |
                 ((unsigned long long)__float_as_uint(xs[p1]) << 32);
        py2[q] = (unsigned long long)__float_as_uint(ys[p0]) |
                 ((unsigned long long)__float_as_uint(ys[p1]) << 32);
        pz2[q] = (unsigned long long)__float_as_uint(zs[p0]) |
                 ((unsigned long long)__float_as_uint(zs[p1]) << 32);
        dmin[2 * q] = 3.0e38f; dmin[2 * q + 1] = 3.0e38f;
    }
    float cx = xs[0], cy = ys[0], cz = zs[0];
    if (t == 0) {
        float* o = &new_xyz[(size_t)b * SQ * 3];
        o[0] = cx; o[1] = cy; o[2] = cz;
    }

    for (int i = 1; i < SQ; i++) {
        unsigned long long ncx = bcast2(-cx), ncy = bcast2(-cy), ncz = bcast2(-cz);
        unsigned bb[8];
#pragma unroll
        for (int q = 0; q < 4; q++) {
            unsigned long long dx = add2(px2[q], ncx);
            unsigned long long dy = add2(py2[q], ncy);
            unsigned long long dz = add2(pz2[q], ncz);
            unsigned long long d2 = mul2(dx, dx);
            d2 = fma2(dy, dy, d2);
            d2 = fma2(dz, dz, d2);
            float2 f = unpk2(d2);
            float a = fminf(dmin[2 * q], f.x);
            float c = fminf(dmin[2 * q + 1], f.y);
            dmin[2 * q] = a; dmin[2 * q + 1] = c;
            bb[2 * q] = __float_as_uint(a);
            bb[2 * q + 1] = __float_as_uint(c);
        }
        unsigned m01 = max(bb[0], bb[1]), m23 = max(bb[2], bb[3]);
        unsigned m45 = max(bb[4], bb[5]), m67 = max(bb[6], bb[7]);
        unsigned mloc = max(max(m01, m23), max(m45, m67));
        unsigned vmax = __reduce_max_sync(0xffffffffu, mloc);
        unsigned mk = 0;
#pragma unroll
        for (int r = 0; r < 8; r++) mk |= (bb[r] == vmax) ? (1u << r) : 0u;
        int pl = mk ? (t + ((__ffs(mk) - 1) << 9)) : 0x7fffffff;
        int imin = __reduce_min_sync(0xffffffffu, pl);

        const int buf = i & 1;
        if (lane == 0) { sv[buf][warp] = vmax; si[buf][warp] = imin; }
        __syncthreads();
        unsigned vb = sv[buf][lane & 15];
        int      ib = si[buf][lane & 15];
        unsigned vm = __reduce_max_sync(0xffffffffu, vb);
        int c2 = (vb == vm) ? ib : 0x7fffffff;
        int im = __reduce_min_sync(0xffffffffu, c2);
        cx = xs[im]; cy = ys[im]; cz = zs[im];
        if (t == 0) {
            float* o = &new_xyz[((size_t)b * SQ + i) * 3];
            o[0] = cx; o[1] = cy; o[2] = cz;
        }
    }
}

// ---------------------------------------------------------------------------
// Kernel 2: ball query (unchanged).
// ---------------------------------------------------------------------------
__global__ __launch_bounds__(256) void ball_kernel(
    const float* __restrict__ xyz, const float* __restrict__ new_xyz)
{
    const int blk = blockIdx.x;
    const int b = blk >> 7;
    const int t = threadIdx.x;
    const int lane = t & 31;
    const int warp = t >> 5;
    const int s = ((blk & 127) << 3) + warp;

    extern __shared__ float sm[];
    float* xs = sm;
    float* ys = sm + NQ;
    float* zs = sm + 2 * NQ;
    unsigned long long* cand =
        (unsigned long long*)(sm + 3 * NQ) + (size_t)warp * CAND_CAP;

    const float* xb = xyz + (size_t)b * NQ * 3;
    for (int idx = t; idx < NQ * 3; idx += 256) {
        float v = xb[idx];
        int p = idx / 3;
        int j = idx - 3 * p;
        if (j == 0) xs[p] = v; else if (j == 1) ys[p] = v; else zs[p] = v;
    }
    __syncthreads();

    const float* cc = &new_xyz[((size_t)b * SQ + s) * 3];
    const float cx = cc[0], cy = cc[1], cz = cc[2];

    int cnt = 0;
#pragma unroll 4
    for (int j = 0; j < NQ / 32; j++) {
        int p = (j << 5) + lane;
        float dx = xs[p] - cx, dy = ys[p] - cy, dz = zs[p] - cz;
        float d = dx * dx;
        d = fmaf(dy, dy, d);
        d = fmaf(dz, dz, d);
        bool in = (d <= 0.04f);
        unsigned m = __ballot_sync(0xffffffffu, in);
        int pos = cnt + __popc(m & ((1u << lane) - 1u));
        if (in && pos < CAND_CAP)
            cand[pos] = ((unsigned long long)__float_as_uint(d) << 32) |
                        (unsigned)p;
        cnt += __popc(m);
    }
    __syncwarp();
    int L = cnt < CAND_CAP ? cnt : CAND_CAP;

    int* go = &g_group_idx[((size_t)b * SQ + s) * KQ];

    for (int c = lane; c < L; c += 32) {
        unsigned long long key = cand[c];
        int rank = 0;
        for (int j = 0; j < L; j++) rank += (cand[j] < key);
        if (rank < KQ) go[rank] = (int)(unsigned)key;
    }

    if (L < KQ) {
        int fillpos = L;
        for (int base = 0; base < NQ && fillpos < KQ; base += 32) {
            int p = base + lane;
            float dx = xs[p] - cx, dy = ys[p] - cy, dz = zs[p] - cz;
            float d = dx * dx;
            d = fmaf(dy, dy, d);
            d = fmaf(dz, dz, d);
            bool ob = (d > 0.04f);
            unsigned m = __ballot_sync(0xffffffffu, ob);
            int pos = fillpos + __popc(m & ((1u << lane) - 1u));
            if (ob && pos < KQ) go[pos] = p;
            fillpos += __popc(m);
        }
    }
}

// ---------------------------------------------------------------------------
// Kernel 3: fused MLP, fp16 m16n8k16, PING-PONG A buffers (4 barriers),
// f' in regs, launch_bounds(256,4) for 4 blocks/SM.
// ---------------------------------------------------------------------------
template<int KT>
__device__ __forceinline__ void gemm_layer(
    const unsigned* __restrict__ P, const uint4* __restrict__ Wp,
    int lane, int wbase, int mibase, float acc[2][4][4])
{
#pragma unroll
    for (int mi = 0; mi < 2; mi++)
#pragma unroll
        for (int nt = 0; nt < 4; nt++)
#pragma unroll
            for (int q = 0; q < 4; q++) acc[mi][nt][q] = 0.f;

#pragma unroll
    for (int kt = 0; kt < KT; kt++) {
        uint4 a[2];
#pragma unroll
        for (int mi = 0; mi < 2; mi++)
            a[mi] = *(const uint4*)&P[(((kt * 4 + mibase + mi) * 32 + lane) << 2)];
        uint4 w01 = __ldg(&Wp[kt * 256 + wbase]);
        uint4 w23 = __ldg(&Wp[kt * 256 + wbase + 32]);
#pragma unroll
        for (int mi = 0; mi < 2; mi++) {
            mma_f16(acc[mi][0][0], acc[mi][0][1], acc[mi][0][2], acc[mi][0][3],
                    a[mi].x, a[mi].y, a[mi].z, a[mi].w, w01.x, w01.y);
            mma_f16(acc[mi][1][0], acc[mi][1][1], acc[mi][1][2], acc[mi][1][3],
                    a[mi].x, a[mi].y, a[mi].z, a[mi].w, w01.z, w01.w);
            mma_f16(acc[mi][2][0], acc[mi][2][1], acc[mi][2][2], acc[mi][2][3],
                    a[mi].x, a[mi].y, a[mi].z, a[mi].w, w23.x, w23.y);
            mma_f16(acc[mi][3][0], acc[mi][3][1], acc[mi][3][2], acc[mi][3][3],
                    a[mi].x, a[mi].y, a[mi].z, a[mi].w, w23.z, w23.w);
        }
    }
}

__global__ __launch_bounds__(256, 4) void mlp_kernel(
    const float* __restrict__ xyz, const float* __restrict__ feats,
    const float* __restrict__ new_xyz,
    const float* __restrict__ b1, const float* __restrict__ b2,
    const float* __restrict__ b3, const float* __restrict__ b4,
    float* __restrict__ f_out)
{
    const int bs0 = blockIdx.x << 1;
    const int b   = bs0 >> 10;
    const int t   = threadIdx.x;
    const int lane = t & 31;
    const int warp = t >> 5;
    const int wm  = warp >> 2;
    const int wn  = warp & 3;
    const int g  = lane >> 2;
    const int tg = lane & 3;
    const int nb = wn << 5;
    const int mibase = wm << 1;
    const int wbase = wn * 64 + lane;

    extern __shared__ unsigned dynsm[];
    unsigned* P0  = dynsm;                        // buffer A (9kt)
    unsigned* P1  = dynsm + PWORDS;               // buffer B (9kt)
    float*    xns = (float*)(dynsm + 2 * PWORDS); // 192
    __shared__ int   gi[2 * KQ];
    __shared__ float ctr[6];

    if (t < 2 * KQ) gi[t] = g_group_idx[(size_t)bs0 * KQ + t];
    if (t >= 64 && t < 70) ctr[t - 64] = new_xyz[(size_t)bs0 * 3 + (t - 64)];
    __syncthreads();

    // ---- gather A1 into P0: feats pi0-31, xn pi32-33, zero 34-39 ----
    const float* fb = feats + (size_t)b * NQ * CQ;
    for (int e = t; e < 64 * 32; e += 256) {
        int r = e >> 5, p = e & 31;
        float2 v = *(const float2*)(fb + (size_t)gi[r] * CQ + 2 * p);
        P0[pidx16(r, p)] = f2h2(v.x, v.y);
    }
    if (t < 64) {    // one thread per row: xyz gather + xn + pads
        int r = t;
        int cen = r >> 5;
        const float* pr = &xyz[((size_t)b * NQ + gi[r]) * 3];
        float x0 = pr[0] - ctr[cen * 3 + 0];
        float x1 = pr[1] - ctr[cen * 3 + 1];
        float x2 = pr[2] - ctr[cen * 3 + 2];
        xns[cen * 96 +  0 + (r & 31)] = x0;
        xns[cen * 96 + 32 + (r & 31)] = x1;
        xns[cen * 96 + 64 + (r & 31)] = x2;
        P0[pidx16(r, 32)] = f2h2(x0, x1);
        P0[pidx16(r, 33)] = f2h2(x2, 0.f);
#pragma unroll
        for (int pi = 34; pi < 40; pi++) P0[pidx16(r, pi)] = 0u;
    }
    __syncthreads();

    float acc[2][4][4];

    // ----- Layer 1: 80(pad) -> 128, relu; epi -> P1 (no WAR barrier) -----
    gemm_layer<5>(P0, g_W1h, lane, wbase, mibase, acc);
#pragma unroll
    for (int nt = 0; nt < 4; nt++) {
        int cc = nb + (nt << 3) + 2 * tg;
        int pi = cc >> 1;
        float bb0 = __ldg(&b1[cc]), bb1 = __ldg(&b1[cc + 1]);
#pragma unroll
        for (int mi = 0; mi < 2; mi++) {
            int r = (mibase + mi) * 16 + g;
            P1[pidx16(r, pi)] = f2h2(fmaxf(acc[mi][nt][0] + bb0, 0.f),
                                     fmaxf(acc[mi][nt][1] + bb1, 0.f));
            P1[pidx16(r + 8, pi)] = f2h2(fmaxf(acc[mi][nt][2] + bb0, 0.f),
                                         fmaxf(acc[mi][nt][3] + bb1, 0.f));
        }
    }
    __syncthreads();

    // ----- Layer 2: 128 -> 128, relu -> f' in regs; A2 -> P0 -----
    gemm_layer<8>(P1, g_W2h, lane, wbase, mibase, acc);
    unsigned fpk[2][4][2];
    float2   cm[4];
#pragma unroll
    for (int nt = 0; nt < 4; nt++) {
        int cc = nb + (nt << 3) + 2 * tg;
        float bb0 = __ldg(&b2[cc]), bb1 = __ldg(&b2[cc + 1]);
        float2 cs = make_float2(0.f, 0.f);
#pragma unroll
        for (int mi = 0; mi < 2; mi++) {
            fpk[mi][nt][0] = f2h2(fmaxf(acc[mi][nt][0] + bb0, 0.f),
                                  fmaxf(acc[mi][nt][1] + bb1, 0.f));
            fpk[mi][nt][1] = f2h2(fmaxf(acc[mi][nt][2] + bb0, 0.f),
                                  fmaxf(acc[mi][nt][3] + bb1, 0.f));
            float2 f0 = h22f2(fpk[mi][nt][0]);
            float2 f1 = h22f2(fpk[mi][nt][1]);
            cs.x += f0.x + f1.x;
            cs.y += f0.y + f1.y;
        }
#pragma unroll
        for (int off = 4; off < 32; off <<= 1) {
            cs.x += __shfl_xor_sync(0xffffffffu, cs.x, off);
            cs.y += __shfl_xor_sync(0xffffffffu, cs.y, off);
        }
        cm[nt] = make_float2(cs.x * (1.f / 32.f), cs.y * (1.f / 32.f));
    }

    // ---- A2 into P0 (P0 reads long finished): f'-mean pi0-63, xn 64-65 ----
#pragma unroll
    for (int nt = 0; nt < 4; nt++) {
        int cc = nb + (nt << 3) + 2 * tg;
        int pi = cc >> 1;
#pragma unroll
        for (int mi = 0; mi < 2; mi++) {
            int r = (mibase + mi) * 16 + g;
            float2 f0 = h22f2(fpk[mi][nt][0]);
            float2 f1 = h22f2(fpk[mi][nt][1]);
            P0[pidx16(r, pi)]     = f2h2(f0.x - cm[nt].x, f0.y - cm[nt].y);
            P0[pidx16(r + 8, pi)] = f2h2(f1.x - cm[nt].x, f1.y - cm[nt].y);
        }
    }
    if (t < 64) {
        int r = t;
        int cen = r >> 5;
        float x0 = xns[cen * 96 +  0 + (r & 31)];
        float x1 = xns[cen * 96 + 32 + (r & 31)];
        float x2 = xns[cen * 96 + 64 + (r & 31)];
        P0[pidx16(r, 64)] = f2h2(x0, x1);
        P0[pidx16(r, 65)] = f2h2(x2, 0.f);
#pragma unroll
        for (int pi = 66; pi < 72; pi++) P0[pidx16(r, pi)] = 0u;
    }
    __syncthreads();

    // ----- Layer 3: 144(pad) -> 128, relu; epi -> P1 -----
    gemm_layer<9>(P0, g_W3h, lane, wbase, mibase, acc);
#pragma unroll
    for (int nt = 0; nt < 4; nt++) {
        int cc = nb + (nt << 3) + 2 * tg;
        int pi = cc >> 1;
        float bb0 = __ldg(&b3[cc]), bb1 = __ldg(&b3[cc + 1]);
#pragma unroll
        for (int mi = 0; mi < 2; mi++) {
            int r = (mibase + mi) * 16 + g;
            P1[pidx16(r, pi)] = f2h2(fmaxf(acc[mi][nt][0] + bb0, 0.f),
                                     fmaxf(acc[mi][nt][1] + bb1, 0.f));
            P1[pidx16(r + 8, pi)] = f2h2(fmaxf(acc[mi][nt][2] + bb0, 0.f),
                                         fmaxf(acc[mi][nt][3] + bb1, 0.f));
        }
    }
    __syncthreads();

    // ----- Layer 4: 128 -> 128, sigmoid; weighted sum from fpk regs -----
    gemm_layer<8>(P1, g_W4h, lane, wbase, mibase, acc);
#pragma unroll
    for (int nt = 0; nt < 4; nt++) {
        int cc = nb + (nt << 3) + 2 * tg;
        float bb0 = __ldg(&b4[cc]), bb1 = __ldg(&b4[cc + 1]);
        float s0 = 0.f, s1 = 0.f;
#pragma unroll
        for (int mi = 0; mi < 2; mi++) {
            float2 f0 = h22f2(fpk[mi][nt][0]);
            float2 f1 = h22f2(fpk[mi][nt][1]);
            float a0 = 1.f / (1.f + __expf(-(acc[mi][nt][0] + bb0)));
            float a1 = 1.f / (1.f + __expf(-(acc[mi][nt][1] + bb1)));
            float a2 = 1.f / (1.f + __expf(-(acc[mi][nt][2] + bb0)));
            float a3 = 1.f / (1.f + __expf(-(acc[mi][nt][3] + bb1)));
            s0 = fmaf(a0, f0.x, s0);
            s1 = fmaf(a1, f0.y, s1);
            s0 = fmaf(a2, f1.x, s0);
            s1 = fmaf(a3, f1.y, s1);
        }
#pragma unroll
        for (int off = 4; off < 32; off <<= 1) {
            s0 += __shfl_xor_sync(0xffffffffu, s0, off);
            s1 += __shfl_xor_sync(0xffffffffu, s1, off);
        }
        if (g == 0) {
            f_out[((size_t)bs0 + wm) * HQ + cc]     = s0;
            f_out[((size_t)bs0 + wm) * HQ + cc + 1] = s1;
        }
    }
}

// ---------------------------------------------------------------------------
extern "C" void kernel_launch(void* const* d_in, const int* in_sizes, int n_in,
                              void* d_out, int out_size)
{
    const float* xyz   = (const float*)d_in[0];
    const float* feats = (const float*)d_in[1];
    const float* W1 = (const float*)d_in[2];
    const float* b1 = (const float*)d_in[3];
    const float* W2 = (const float*)d_in[4];
    const float* b2 = (const float*)d_in[5];
    const float* W3 = (const float*)d_in[6];
    const float* b3 = (const float*)d_in[7];
    const float* W4 = (const float*)d_in[8];
    const float* b4 = (const float*)d_in[9];

    float* out     = (float*)d_out;
    float* new_xyz = out;
    float* f_out   = out + (size_t)BQ * SQ * 3;

    const int fps_smem  = 3 * NQ * sizeof(float);                       // 48KB
    const int ball_smem = fps_smem + 8 * CAND_CAP * sizeof(long long);  // 96KB
    const int mlp_smem  = (2 * PWORDS + 192) * 4;                       // ~37KB
    cudaFuncSetAttribute(fps_kernel,
                         cudaFuncAttributeMaxDynamicSharedMemorySize, fps_smem);
    cudaFuncSetAttribute(ball_kernel,
                         cudaFuncAttributeMaxDynamicSharedMemorySize, ball_smem);
    cudaFuncSetAttribute(mlp_kernel,
                         cudaFuncAttributeMaxDynamicSharedMemorySize, mlp_smem);

    cvt_w_kernel<<<(9 * 256 + 255) / 256, 256>>>(W1, W2, W3, W4);
    fps_kernel <<<BQ, 512, fps_smem>>>(xyz, new_xyz);
    ball_kernel<<<(BQ * SQ) / 8, 256, ball_smem>>>(xyz, new_xyz);
    mlp_kernel <<<(BQ * SQ) / 2, 256, mlp_smem>>>(xyz, feats, new_xyz,
                                                  b1, b2, b3, b4, f_out);
}

// round 14
// speedup vs baseline: 1.0610x; 1.0610x over previous
#include <cuda_runtime.h>
#include <cuda_fp16.h>
#include <math.h>

#define BQ 16
#define NQ 4096
#define SQ 1024
#define KQ 32
#define CQ 64
#define HQ 128
#define CAND_CAP 768
#define PWORDS 4608   // 9kt * 4mi * 32 lanes * 4 words (one A buffer)

__device__ int g_group_idx[BQ * SQ * KQ];

// fp16 B-fragments packed as uint4 (two adjacent nt fragments per thread):
// index = (kt*8 + wn*2 + ntp)*32 + lane;  lane = g*4+tg.
__device__ uint4 g_W1h[5 * 256];
__device__ uint4 g_W2h[8 * 256];
__device__ uint4 g_W3h[9 * 256];
__device__ uint4 g_W4h[8 * 256];

__device__ __forceinline__ unsigned f2h2(float lo, float hi) {
    __half2 h = __floats2half2_rn(lo, hi);
    return *(unsigned*)&h;
}
__device__ __forceinline__ float2 h22f2(unsigned u) {
    __half2 h = *(__half2*)&u;
    return __half22float2(h);
}
__device__ __forceinline__ void mma_f16(
    float& d0, float& d1, float& d2, float& d3,
    unsigned a0, unsigned a1, unsigned a2, unsigned a3,
    unsigned b0, unsigned b1)
{
    asm("mma.sync.aligned.m16n8k16.row.col.f32.f16.f16.f32 "
        "{%0,%1,%2,%3}, {%4,%5,%6,%7}, {%8,%9}, {%0,%1,%2,%3};"
        : "+f"(d0), "+f"(d1), "+f"(d2), "+f"(d3)
        : "r"(a0), "r"(a1), "r"(a2), "r"(a3), "r"(b0), "r"(b1));
}

// packed f32x2 helpers (FPS)
__device__ __forceinline__ unsigned long long add2(
    unsigned long long a, unsigned long long b)
{
    unsigned long long d;
    asm("add.rn.f32x2 %0, %1, %2;" : "=l"(d) : "l"(a), "l"(b));
    return d;
}
__device__ __forceinline__ unsigned long long mul2(
    unsigned long long a, unsigned long long b)
{
    unsigned long long d;
    asm("mul.rn.f32x2 %0, %1, %2;" : "=l"(d) : "l"(a), "l"(b));
    return d;
}
__device__ __forceinline__ unsigned long long fma2(
    unsigned long long a, unsigned long long b, unsigned long long c)
{
    unsigned long long d;
    asm("fma.rn.f32x2 %0, %1, %2, %3;" : "=l"(d) : "l"(a), "l"(b), "l"(c));
    return d;
}
__device__ __forceinline__ unsigned long long bcast2(float w)
{
    unsigned long long d; unsigned u = __float_as_uint(w);
    asm("mov.b64 %0, {%1, %1};" : "=l"(d) : "r"(u));
    return d;
}
__device__ __forceinline__ float2 unpk2(unsigned long long a)
{
    float2 f;
    asm("mov.b64 {%0, %1}, %2;" : "=f"(f.x), "=f"(f.y) : "l"(a));
    return f;
}

// fragment-major A index for m16n8k16 (word = fp16x2 pair):
__device__ __forceinline__ int pidx16(int r, int pi) {
    int kt = pi >> 3, pp = pi & 7;
    int ls = (r & 7) * 4 + (pp & 3);
    int reg = ((r >> 3) & 1) + 2 * ((pp >> 2) & 1);
    return (((kt * 4 + (r >> 4)) * 32 + ls) << 2) + reg;
}

// ---------------------------------------------------------------------------
// Kernel 0: pack weights into per-thread fp16 uint4 B-fragments w/ col perm.
// ---------------------------------------------------------------------------
__device__ __forceinline__ float getw(const float* __restrict__ W,
                                      int k, int n, int mode)
{
    int r;
    if (mode == 0)      r = (k < 128) ? k       : -1;
    else if (mode == 1) r = (k < 64)  ? k + 3   : (k < 67  ? k - 64  : -1);
    else                r = (k < 128) ? k + 3   : (k < 131 ? k - 128 : -1);
    return (r >= 0) ? W[r * 128 + n] : 0.f;
}
__device__ __forceinline__ void pack16(int i, int KT, int mode,
                                       const float* __restrict__ W, uint4* out)
{
    if (i < KT * 256) {
        int kt = i >> 8, rem = i & 255;
        int w = rem >> 5, lane = rem & 31;
        int wn = w >> 1, ntp = w & 1;
        int g = lane >> 2, tg = lane & 3;
        int nc0 = wn * 32 + (2 * ntp) * 8 + g;
        int nc1 = nc0 + 8;
        int k0 = 16 * kt + 2 * tg;
        out[i] = make_uint4(
            f2h2(getw(W, k0,     nc0, mode), getw(W, k0 + 1, nc0, mode)),
            f2h2(getw(W, k0 + 8, nc0, mode), getw(W, k0 + 9, nc0, mode)),
            f2h2(getw(W, k0,     nc1, mode), getw(W, k0 + 1, nc1, mode)),
            f2h2(getw(W, k0 + 8, nc1, mode), getw(W, k0 + 9, nc1, mode)));
    }
}
__global__ void cvt_w_kernel(const float* __restrict__ W1,
                             const float* __restrict__ W2,
                             const float* __restrict__ W3,
                             const float* __restrict__ W4)
{
    int i = blockIdx.x * 256 + threadIdx.x;
    pack16(i, 5, 1, W1, g_W1h);
    pack16(i, 8, 0, W2, g_W2h);
    pack16(i, 9, 2, W3, g_W3h);
    pack16(i, 8, 0, W4, g_W4h);
}

// ---------------------------------------------------------------------------
// Kernel 1: FPS (unchanged — math must stay bit-identical).
// ---------------------------------------------------------------------------
__global__ __launch_bounds__(512) void fps_kernel(
    const float* __restrict__ xyz, float* __restrict__ new_xyz)
{
    const int b = blockIdx.x;
    const int t = threadIdx.x;
    const int lane = t & 31;
    const int warp = t >> 5;
    extern __shared__ float sm[];
    float* xs = sm;
    float* ys = sm + NQ;
    float* zs = sm + 2 * NQ;
    __shared__ unsigned sv[2][16];
    __shared__ int      si[2][16];

    const float* xb = xyz + (size_t)b * NQ * 3;
    for (int idx = t; idx < NQ * 3; idx += 512) {
        float v = xb[idx];
        int p = idx / 3;
        int j = idx - 3 * p;
        if (j == 0) xs[p] = v; else if (j == 1) ys[p] = v; else zs[p] = v;
    }
    __syncthreads();

    unsigned long long px2[4], py2[4], pz2[4];
    float dmin[8];
#pragma unroll
    for (int q = 0; q < 4; q++) {
        int p0 = t + ((2 * q) << 9), p1 = t + ((2 * q + 1) << 9);
        px2[q] = (unsigned long long)__float_as_uint(xs[p0]) |
                 ((unsigned long long)__float_as_uint(xs[p1]) << 32);
        py2[q] = (unsigned long long)__float_as_uint(ys[p0]) |
                 ((unsigned long long)__float_as_uint(ys[p1]) << 32);
        pz2[q] = (unsigned long long)__float_as_uint(zs[p0]) |
                 ((unsigned long long)__float_as_uint(zs[p1]) << 32);
        dmin[2 * q] = 3.0e38f; dmin[2 * q + 1] = 3.0e38f;
    }
    float cx = xs[0], cy = ys[0], cz = zs[0];
    if (t == 0) {
        float* o = &new_xyz[(size_t)b * SQ * 3];
        o[0] = cx; o[1] = cy; o[2] = cz;
    }

    for (int i = 1; i < SQ; i++) {
        unsigned long long ncx = bcast2(-cx), ncy = bcast2(-cy), ncz = bcast2(-cz);
        unsigned bb[8];
#pragma unroll
        for (int q = 0; q < 4; q++) {
            unsigned long long dx = add2(px2[q], ncx);
            unsigned long long dy = add2(py2[q], ncy);
            unsigned long long dz = add2(pz2[q], ncz);
            unsigned long long d2 = mul2(dx, dx);
            d2 = fma2(dy, dy, d2);
            d2 = fma2(dz, dz, d2);
            float2 f = unpk2(d2);
            float a = fminf(dmin[2 * q], f.x);
            float c = fminf(dmin[2 * q + 1], f.y);
            dmin[2 * q] = a; dmin[2 * q + 1] = c;
            bb[2 * q] = __float_as_uint(a);
            bb[2 * q + 1] = __float_as_uint(c);
        }
        unsigned m01 = max(bb[0], bb[1]), m23 = max(bb[2], bb[3]);
        unsigned m45 = max(bb[4], bb[5]), m67 = max(bb[6], bb[7]);
        unsigned mloc = max(max(m01, m23), max(m45, m67));
        unsigned vmax = __reduce_max_sync(0xffffffffu, mloc);
        unsigned mk = 0;
#pragma unroll
        for (int r = 0; r < 8; r++) mk |= (bb[r] == vmax) ? (1u << r) : 0u;
        int pl = mk ? (t + ((__ffs(mk) - 1) << 9)) : 0x7fffffff;
        int imin = __reduce_min_sync(0xffffffffu, pl);

        const int buf = i & 1;
        if (lane == 0) { sv[buf][warp] = vmax; si[buf][warp] = imin; }
        __syncthreads();
        unsigned vb = sv[buf][lane & 15];
        int      ib = si[buf][lane & 15];
        unsigned vm = __reduce_max_sync(0xffffffffu, vb);
        int c2 = (vb == vm) ? ib : 0x7fffffff;
        int im = __reduce_min_sync(0xffffffffu, c2);
        cx = xs[im]; cy = ys[im]; cz = zs[im];
        if (t == 0) {
            float* o = &new_xyz[((size_t)b * SQ + i) * 3];
            o[0] = cx; o[1] = cy; o[2] = cz;
        }
    }
}

// ---------------------------------------------------------------------------
// Kernel 2: ball query (unchanged).
// ---------------------------------------------------------------------------
__global__ __launch_bounds__(256) void ball_kernel(
    const float* __restrict__ xyz, const float* __restrict__ new_xyz)
{
    const int blk = blockIdx.x;
    const int b = blk >> 7;
    const int t = threadIdx.x;
    const int lane = t & 31;
    const int warp = t >> 5;
    const int s = ((blk & 127) << 3) + warp;

    extern __shared__ float sm[];
    float* xs = sm;
    float* ys = sm + NQ;
    float* zs = sm + 2 * NQ;
    unsigned long long* cand =
        (unsigned long long*)(sm + 3 * NQ) + (size_t)warp * CAND_CAP;

    const float* xb = xyz + (size_t)b * NQ * 3;
    for (int idx = t; idx < NQ * 3; idx += 256) {
        float v = xb[idx];
        int p = idx / 3;
        int j = idx - 3 * p;
        if (j == 0) xs[p] = v; else if (j == 1) ys[p] = v; else zs[p] = v;
    }
    __syncthreads();

    const float* cc = &new_xyz[((size_t)b * SQ + s) * 3];
    const float cx = cc[0], cy = cc[1], cz = cc[2];

    int cnt = 0;
#pragma unroll 4
    for (int j = 0; j < NQ / 32; j++) {
        int p = (j << 5) + lane;
        float dx = xs[p] - cx, dy = ys[p] - cy, dz = zs[p] - cz;
        float d = dx * dx;
        d = fmaf(dy, dy, d);
        d = fmaf(dz, dz, d);
        bool in = (d <= 0.04f);
        unsigned m = __ballot_sync(0xffffffffu, in);
        int pos = cnt + __popc(m & ((1u << lane) - 1u));
        if (in && pos < CAND_CAP)
            cand[pos] = ((unsigned long long)__float_as_uint(d) << 32) |
                        (unsigned)p;
        cnt += __popc(m);
    }
    __syncwarp();
    int L = cnt < CAND_CAP ? cnt : CAND_CAP;

    int* go = &g_group_idx[((size_t)b * SQ + s) * KQ];

    for (int c = lane; c < L; c += 32) {
        unsigned long long key = cand[c];
        int rank = 0;
        for (int j = 0; j < L; j++) rank += (cand[j] < key);
        if (rank < KQ) go[rank] = (int)(unsigned)key;
    }

    if (L < KQ) {
        int fillpos = L;
        for (int base = 0; base < NQ && fillpos < KQ; base += 32) {
            int p = base + lane;
            float dx = xs[p] - cx, dy = ys[p] - cy, dz = zs[p] - cz;
            float d = dx * dx;
            d = fmaf(dy, dy, d);
            d = fmaf(dz, dz, d);
            bool ob = (d > 0.04f);
            unsigned m = __ballot_sync(0xffffffffu, ob);
            int pos = fillpos + __popc(m & ((1u << lane) - 1u));
            if (ob && pos < KQ) go[pos] = p;
            fillpos += __popc(m);
        }
    }
}

// ---------------------------------------------------------------------------
// Kernel 3: fused MLP, fp16 m16n8k16, PING-PONG A buffers (4 barriers),
// f' in regs. launch_bounds(256,3): NO register cap -> zero spills.
// ---------------------------------------------------------------------------
template<int KT>
__device__ __forceinline__ void gemm_layer(
    const unsigned* __restrict__ P, const uint4* __restrict__ Wp,
    int lane, int wbase, int mibase, float acc[2][4][4])
{
#pragma unroll
    for (int mi = 0; mi < 2; mi++)
#pragma unroll
        for (int nt = 0; nt < 4; nt++)
#pragma unroll
            for (int q = 0; q < 4; q++) acc[mi][nt][q] = 0.f;

#pragma unroll
    for (int kt = 0; kt < KT; kt++) {
        uint4 a[2];
#pragma unroll
        for (int mi = 0; mi < 2; mi++)
            a[mi] = *(const uint4*)&P[(((kt * 4 + mibase + mi) * 32 + lane) << 2)];
        uint4 w01 = __ldg(&Wp[kt * 256 + wbase]);
        uint4 w23 = __ldg(&Wp[kt * 256 + wbase + 32]);
#pragma unroll
        for (int mi = 0; mi < 2; mi++) {
            mma_f16(acc[mi][0][0], acc[mi][0][1], acc[mi][0][2], acc[mi][0][3],
                    a[mi].x, a[mi].y, a[mi].z, a[mi].w, w01.x, w01.y);
            mma_f16(acc[mi][1][0], acc[mi][1][1], acc[mi][1][2], acc[mi][1][3],
                    a[mi].x, a[mi].y, a[mi].z, a[mi].w, w01.z, w01.w);
            mma_f16(acc[mi][2][0], acc[mi][2][1], acc[mi][2][2], acc[mi][2][3],
                    a[mi].x, a[mi].y, a[mi].z, a[mi].w, w23.x, w23.y);
            mma_f16(acc[mi][3][0], acc[mi][3][1], acc[mi][3][2], acc[mi][3][3],
                    a[mi].x, a[mi].y, a[mi].z, a[mi].w, w23.z, w23.w);
        }
    }
}

__global__ __launch_bounds__(256, 3) void mlp_kernel(
    const float* __restrict__ xyz, const float* __restrict__ feats,
    const float* __restrict__ new_xyz,
    const float* __restrict__ b1, const float* __restrict__ b2,
    const float* __restrict__ b3, const float* __restrict__ b4,
    float* __restrict__ f_out)
{
    const int bs0 = blockIdx.x << 1;
    const int b   = bs0 >> 10;
    const int t   = threadIdx.x;
    const int lane = t & 31;
    const int warp = t >> 5;
    const int wm  = warp >> 2;
    const int wn  = warp & 3;
    const int g  = lane >> 2;
    const int tg = lane & 3;
    const int nb = wn << 5;
    const int mibase = wm << 1;
    const int wbase = wn * 64 + lane;

    extern __shared__ unsigned dynsm[];
    unsigned* P0  = dynsm;                        // buffer A (9kt)
    unsigned* P1  = dynsm + PWORDS;               // buffer B (9kt)
    float*    xns = (float*)(dynsm + 2 * PWORDS); // 192
    __shared__ int   gi[2 * KQ];
    __shared__ float ctr[6];

    if (t < 2 * KQ) gi[t] = g_group_idx[(size_t)bs0 * KQ + t];
    if (t >= 64 && t < 70) ctr[t - 64] = new_xyz[(size_t)bs0 * 3 + (t - 64)];
    __syncthreads();

    // ---- gather A1 into P0: feats pi0-31, xn pi32-33, zero 34-39 ----
    const float* fb = feats + (size_t)b * NQ * CQ;
    for (int e = t; e < 64 * 32; e += 256) {
        int r = e >> 5, p = e & 31;
        float2 v = *(const float2*)(fb + (size_t)gi[r] * CQ + 2 * p);
        P0[pidx16(r, p)] = f2h2(v.x, v.y);
    }
    if (t < 64) {    // one thread per row: xyz gather + xn + pads
        int r = t;
        int cen = r >> 5;
        const float* pr = &xyz[((size_t)b * NQ + gi[r]) * 3];
        float x0 = pr[0] - ctr[cen * 3 + 0];
        float x1 = pr[1] - ctr[cen * 3 + 1];
        float x2 = pr[2] - ctr[cen * 3 + 2];
        xns[cen * 96 +  0 + (r & 31)] = x0;
        xns[cen * 96 + 32 + (r & 31)] = x1;
        xns[cen * 96 + 64 + (r & 31)] = x2;
        P0[pidx16(r, 32)] = f2h2(x0, x1);
        P0[pidx16(r, 33)] = f2h2(x2, 0.f);
#pragma unroll
        for (int pi = 34; pi < 40; pi++) P0[pidx16(r, pi)] = 0u;
    }
    __syncthreads();

    float acc[2][4][4];

    // ----- Layer 1: 80(pad) -> 128, relu; epi -> P1 (no WAR barrier) -----
    gemm_layer<5>(P0, g_W1h, lane, wbase, mibase, acc);
#pragma unroll
    for (int nt = 0; nt < 4; nt++) {
        int cc = nb + (nt << 3) + 2 * tg;
        int pi = cc >> 1;
        float bb0 = __ldg(&b1[cc]), bb1 = __ldg(&b1[cc + 1]);
#pragma unroll
        for (int mi = 0; mi < 2; mi++) {
            int r = (mibase + mi) * 16 + g;
            P1[pidx16(r, pi)] = f2h2(fmaxf(acc[mi][nt][0] + bb0, 0.f),
                                     fmaxf(acc[mi][nt][1] + bb1, 0.f));
            P1[pidx16(r + 8, pi)] = f2h2(fmaxf(acc[mi][nt][2] + bb0, 0.f),
                                         fmaxf(acc[mi][nt][3] + bb1, 0.f));
        }
    }
    __syncthreads();

    // ----- Layer 2: 128 -> 128, relu -> f' in regs; A2 -> P0 -----
    gemm_layer<8>(P1, g_W2h, lane, wbase, mibase, acc);
    unsigned fpk[2][4][2];
    float2   cm[4];
#pragma unroll
    for (int nt = 0; nt < 4; nt++) {
        int cc = nb + (nt << 3) + 2 * tg;
        float bb0 = __ldg(&b2[cc]), bb1 = __ldg(&b2[cc + 1]);
        float2 cs = make_float2(0.f, 0.f);
#pragma unroll
        for (int mi = 0; mi < 2; mi++) {
            fpk[mi][nt][0] = f2h2(fmaxf(acc[mi][nt][0] + bb0, 0.f),
                                  fmaxf(acc[mi][nt][1] + bb1, 0.f));
            fpk[mi][nt][1] = f2h2(fmaxf(acc[mi][nt][2] + bb0, 0.f),
                                  fmaxf(acc[mi][nt][3] + bb1, 0.f));
            float2 f0 = h22f2(fpk[mi][nt][0]);
            float2 f1 = h22f2(fpk[mi][nt][1]);
            cs.x += f0.x + f1.x;
            cs.y += f0.y + f1.y;
        }
#pragma unroll
        for (int off = 4; off < 32; off <<= 1) {
            cs.x += __shfl_xor_sync(0xffffffffu, cs.x, off);
            cs.y += __shfl_xor_sync(0xffffffffu, cs.y, off);
        }
        cm[nt] = make_float2(cs.x * (1.f / 32.f), cs.y * (1.f / 32.f));
    }

    // ---- A2 into P0 (P0 reads long finished): f'-mean pi0-63, xn 64-65 ----
#pragma unroll
    for (int nt = 0; nt < 4; nt++) {
        int cc = nb + (nt << 3) + 2 * tg;
        int pi = cc >> 1;
#pragma unroll
        for (int mi = 0; mi < 2; mi++) {
            int r = (mibase + mi) * 16 + g;
            float2 f0 = h22f2(fpk[mi][nt][0]);
            float2 f1 = h22f2(fpk[mi][nt][1]);
            P0[pidx16(r, pi)]     = f2h2(f0.x - cm[nt].x, f0.y - cm[nt].y);
            P0[pidx16(r + 8, pi)] = f2h2(f1.x - cm[nt].x, f1.y - cm[nt].y);
        }
    }
    if (t < 64) {
        int r = t;
        int cen = r >> 5;
        float x0 = xns[cen * 96 +  0 + (r & 31)];
        float x1 = xns[cen * 96 + 32 + (r & 31)];
        float x2 = xns[cen * 96 + 64 + (r & 31)];
        P0[pidx16(r, 64)] = f2h2(x0, x1);
        P0[pidx16(r, 65)] = f2h2(x2, 0.f);
#pragma unroll
        for (int pi = 66; pi < 72; pi++) P0[pidx16(r, pi)] = 0u;
    }
    __syncthreads();

    // ----- Layer 3: 144(pad) -> 128, relu; epi -> P1 -----
    gemm_layer<9>(P0, g_W3h, lane, wbase, mibase, acc);
#pragma unroll
    for (int nt = 0; nt < 4; nt++) {
        int cc = nb + (nt << 3) + 2 * tg;
        int pi = cc >> 1;
        float bb0 = __ldg(&b3[cc]), bb1 = __ldg(&b3[cc + 1]);
#pragma unroll
        for (int mi = 0; mi < 2; mi++) {
            int r = (mibase + mi) * 16 + g;
            P1[pidx16(r, pi)] = f2h2(fmaxf(acc[mi][nt][0] + bb0, 0.f),
                                     fmaxf(acc[mi][nt][1] + bb1, 0.f));
            P1[pidx16(r + 8, pi)] = f2h2(fmaxf(acc[mi][nt][2] + bb0, 0.f),
                                         fmaxf(acc[mi][nt][3] + bb1, 0.f));
        }
    }
    __syncthreads();

    // ----- Layer 4: 128 -> 128, sigmoid; weighted sum from fpk regs -----
    gemm_layer<8>(P1, g_W4h, lane, wbase, mibase, acc);
#pragma unroll
    for (int nt = 0; nt < 4; nt++) {
        int cc = nb + (nt << 3) + 2 * tg;
        float bb0 = __ldg(&b4[cc]), bb1 = __ldg(&b4[cc + 1]);
        float s0 = 0.f, s1 = 0.f;
#pragma unroll
        for (int mi = 0; mi < 2; mi++) {
            float2 f0 = h22f2(fpk[mi][nt][0]);
            float2 f1 = h22f2(fpk[mi][nt][1]);
            float a0 = 1.f / (1.f + __expf(-(acc[mi][nt][0] + bb0)));
            float a1 = 1.f / (1.f + __expf(-(acc[mi][nt][1] + bb1)));
            float a2 = 1.f / (1.f + __expf(-(acc[mi][nt][2] + bb0)));
            float a3 = 1.f / (1.f + __expf(-(acc[mi][nt][3] + bb1)));
            s0 = fmaf(a0, f0.x, s0);
            s1 = fmaf(a1, f0.y, s1);
            s0 = fmaf(a2, f1.x, s0);
            s1 = fmaf(a3, f1.y, s1);
        }
#pragma unroll
        for (int off = 4; off < 32; off <<= 1) {
            s0 += __shfl_xor_sync(0xffffffffu, s0, off);
            s1 += __shfl_xor_sync(0xffffffffu, s1, off);
        }
        if (g == 0) {
            f_out[((size_t)bs0 + wm) * HQ + cc]     = s0;
            f_out[((size_t)bs0 + wm) * HQ + cc + 1] = s1;
        }
    }
}

// ---------------------------------------------------------------------------
extern "C" void kernel_launch(void* const* d_in, const int* in_sizes, int n_in,
                              void* d_out, int out_size)
{
    const float* xyz   = (const float*)d_in[0];
    const float* feats = (const float*)d_in[1];
    const float* W1 = (const float*)d_in[2];
    const float* b1 = (const float*)d_in[3];
    const float* W2 = (const float*)d_in[4];
    const float* b2 = (const float*)d_in[5];
    const float* W3 = (const float*)d_in[6];
    const float* b3 = (const float*)d_in[7];
    const float* W4 = (const float*)d_in[8];
    const float* b4 = (const float*)d_in[9];

    float* out     = (float*)d_out;
    float* new_xyz = out;
    float* f_out   = out + (size_t)BQ * SQ * 3;

    const int fps_smem  = 3 * NQ * sizeof(float);                       // 48KB
    const int ball_smem = fps_smem + 8 * CAND_CAP * sizeof(long long);  // 96KB
    const int mlp_smem  = (2 * PWORDS + 192) * 4;                       // ~37KB
    cudaFuncSetAttribute(fps_kernel,
                         cudaFuncAttributeMaxDynamicSharedMemorySize, fps_smem);
    cudaFuncSetAttribute(ball_kernel,
                         cudaFuncAttributeMaxDynamicSharedMemorySize, ball_smem);
    cudaFuncSetAttribute(mlp_kernel,
                         cudaFuncAttributeMaxDynamicSharedMemorySize, mlp_smem);

    cvt_w_kernel<<<(9 * 256 + 255) / 256, 256>>>(W1, W2, W3, W4);
    fps_kernel <<<BQ, 512, fps_smem>>>(xyz, new_xyz);
    ball_kernel<<<(BQ * SQ) / 8, 256, ball_smem>>>(xyz, new_xyz);
    mlp_kernel <<<(BQ * SQ) / 2, 256, mlp_smem>>>(xyz, feats, new_xyz,
                                                  b1, b2, b3, b4, f_out);
}